// round 4
// baseline (speedup 1.0000x reference)
#include <cuda_runtime.h>
#include <cuda_bf16.h>
#include <cstdint>

// Problem constants
#define BB 256
#define TT 512
#define NN 128

// ---------------- device scratch ----------------
__device__ float g_E[NN * NN];        // exp(trans)
__device__ float g_transT[NN * NN];   // transT[j][i] = trans[i][j]
__device__ float g_score[BB];
__device__ float g_alpha[(size_t)BB * TT * NN]; // viterbi alphas, 64 MB
__device__ int   g_lasttag[BB];

__device__ __forceinline__ unsigned ordf(float f) {
    unsigned u = __float_as_uint(f);
    return u ^ (((int)u >> 31) | 0x80000000u);
}

__device__ __forceinline__ void ffma2(unsigned long long& d,
                                      unsigned long long a,
                                      unsigned long long b) {
    asm("fma.rn.f32x2 %0, %1, %2, %0;" : "+l"(d) : "l"(a), "l"(b));
}

__device__ __forceinline__ unsigned long long add2(unsigned long long a,
                                                   unsigned long long b) {
    unsigned long long d;
    asm("add.rn.f32x2 %0, %1, %2;" : "=l"(d) : "l"(a), "l"(b));
    return d;
}

__device__ __forceinline__ float lo32(unsigned long long v) {
    return __uint_as_float((unsigned)v);
}
__device__ __forceinline__ float hi32(unsigned long long v) {
    return __uint_as_float((unsigned)(v >> 32));
}

// ---------------- K0: prep -----------------------------------------
__global__ void k_prep(const float* __restrict__ trans, float* __restrict__ out_trans) {
    int idx = blockIdx.x * 256 + threadIdx.x;
    if (idx < NN * NN) {
        float v = trans[idx];
        g_E[idx] = __expf(v);
        int i = idx >> 7, j = idx & 127;
        g_transT[j * NN + i] = v;
        out_trans[idx] = v;
    }
}

// ---------------- K1: sequence score --------------------------------
// tag_ids: JAX silently emits int32 despite int64 declaration.
__global__ __launch_bounds__(256) void k_score(const float* __restrict__ emis,
                                               const int* __restrict__ tags,
                                               const int* __restrict__ mask,
                                               const float* __restrict__ trans) {
    __shared__ float sred[8];
    const int b = blockIdx.x;
    const int tid = threadIdx.x;
    float acc = 0.f;
    const float* eb = emis + (size_t)b * TT * NN;
    const int* tb = tags + (size_t)b * TT;
    const int* mb = mask + (size_t)b * TT;
    for (int t = tid; t < TT; t += 256) {
        int tg = tb[t];
        float mf = (float)mb[t];
        float u = eb[(size_t)t * NN + tg] * mf;
        float bi = 0.f;
        if (t > 0) {
            int tp = tb[t - 1];
            bi = trans[tp * NN + tg] * mf;
        }
        acc += u + bi;
    }
    #pragma unroll
    for (int o = 16; o; o >>= 1) acc += __shfl_xor_sync(0xffffffffu, acc, o);
    if ((tid & 31) == 0) sred[tid >> 5] = acc;
    __syncthreads();
    if (tid == 0) {
        float s = 0.f;
        #pragma unroll
        for (int i = 0; i < 8; i++) s += sred[i];
        g_score[b] = s;
    }
}

// ---------------- K2: fused recurrences ------------------------------
// grid = 512. blockIdx&1 == 0 -> forward (log-norm), == 1 -> viterbi.
// 128 threads; thread j owns output state j and the full matrix column in
// registers. One __syncthreads() per time step.
__global__ __launch_bounds__(128, 3) void k_recur(const float* __restrict__ emis,
                                                  const int* __restrict__ mask,
                                                  const float* __restrict__ trans,
                                                  float* __restrict__ out_ll) {
    const int type = blockIdx.x & 1;
    const int b = blockIdx.x >> 1;
    const int j = threadIdx.x;

    __shared__ __align__(16) float buf[2][NN];
    __shared__ float csm[2];
    __shared__ int smask[TT];

    const float* eb = emis + (size_t)b * TT * NN;
    const int* mb = mask + (size_t)b * TT;

    for (int i = j; i < TT; i += NN) smask[i] = mb[i];

    if (type == 0) {
        // ---------------- forward: alpha'_j = log(sum_i p_i * E_ij) + c + e
        unsigned long long E2[64];
        {
            const float* Ej = g_E + j;
            #pragma unroll
            for (int k = 0; k < 64; k++) {
                unsigned lo = __float_as_uint(Ej[(size_t)(2 * k) * NN]);
                unsigned hi = __float_as_uint(Ej[(size_t)(2 * k + 1) * NN]);
                E2[k] = (unsigned long long)lo | ((unsigned long long)hi << 32);
            }
        }

        float a = eb[j];
        float c = eb[0];
        float e_next = eb[NN + j];
        int sel = 0;
        __syncthreads();             // smask ready

        for (int t = 1; t < TT; t++) {
            buf[sel][j] = __expf(a - c);
            if (j == 0) csm[sel] = a;
            __syncthreads();
            float c_next = csm[sel];

            unsigned long long acc[8];
            #pragma unroll
            for (int q = 0; q < 8; q++) acc[q] = 0ull;
            const ulonglong2* pv = (const ulonglong2*)buf[sel];
            #pragma unroll
            for (int k = 0; k < 32; k++) {
                ulonglong2 v = pv[k];
                ffma2(acc[(2 * k) & 7], v.x, E2[2 * k]);
                ffma2(acc[(2 * k + 1) & 7], v.y, E2[2 * k + 1]);
            }
            float s = 0.f;
            #pragma unroll
            for (int q = 0; q < 8; q++) s += lo32(acc[q]) + hi32(acc[q]);

            float e_cur = e_next;
            if (t + 1 < TT) e_next = eb[(size_t)(t + 1) * NN + j];

            float a_new = __logf(s) + c + e_cur;
            a = smask[t] ? a_new : a;
            c = c_next;
            sel ^= 1;
        }

        // final logsumexp
        buf[0][j] = __expf(a - c);
        __syncthreads();
        if (j < 32) {
            float4 v = ((const float4*)buf[0])[j];
            float tsum = (v.x + v.y) + (v.z + v.w);
            #pragma unroll
            for (int o = 16; o; o >>= 1) tsum += __shfl_xor_sync(0xffffffffu, tsum, o);
            if (j == 0) out_ll[b] = g_score[b] - (__logf(tsum) + c);
        }
    } else {
        // ---------------- viterbi: alpha'_j = max_i(a_i + T_ij) + e
        unsigned long long T2[64];
        {
            const float* Tj = trans + j;
            #pragma unroll
            for (int k = 0; k < 64; k++) {
                unsigned lo = __float_as_uint(Tj[(size_t)(2 * k) * NN]);
                unsigned hi = __float_as_uint(Tj[(size_t)(2 * k + 1) * NN]);
                T2[k] = (unsigned long long)lo | ((unsigned long long)hi << 32);
            }
        }

        float* arow = g_alpha + (size_t)b * TT * NN;
        float a = eb[j];
        buf[0][j] = a;
        arow[j] = a;
        float e_next = eb[NN + j];
        int sel = 0;
        const float NEGINF = -3.402823466e38f;
        __syncthreads();             // buf[0] + smask ready

        for (int t = 1; t < TT; t++) {
            float m[8];
            #pragma unroll
            for (int q = 0; q < 8; q++) m[q] = NEGINF;
            const ulonglong2* av = (const ulonglong2*)buf[sel];
            #pragma unroll
            for (int k = 0; k < 32; k++) {
                ulonglong2 v = av[k];
                unsigned long long w0 = add2(v.x, T2[2 * k]);
                unsigned long long w1 = add2(v.y, T2[2 * k + 1]);
                int q = (4 * k) & 7;
                m[q + 0] = fmaxf(m[q + 0], lo32(w0));
                m[q + 1] = fmaxf(m[q + 1], hi32(w0));
                m[q + 2] = fmaxf(m[q + 2], lo32(w1));
                m[q + 3] = fmaxf(m[q + 3], hi32(w1));
            }
            float bm = fmaxf(fmaxf(fmaxf(m[0], m[1]), fmaxf(m[2], m[3])),
                             fmaxf(fmaxf(m[4], m[5]), fmaxf(m[6], m[7])));

            float e_cur = e_next;
            if (t + 1 < TT) e_next = eb[(size_t)(t + 1) * NN + j];

            float a_new = bm + e_cur;
            a = smask[t] ? a_new : a;
            buf[sel ^ 1][j] = a;
            arow[(size_t)t * NN + j] = a;
            sel ^= 1;
            __syncthreads();
        }

        // last_tag = first argmax over final alphas (in buf[sel])
        if (j < 32) {
            float4 v = ((const float4*)buf[sel])[j];
            float best = v.x; int bi = 4 * j;
            if (v.y > best) { best = v.y; bi = 4 * j + 1; }
            if (v.z > best) { best = v.z; bi = 4 * j + 2; }
            if (v.w > best) { best = v.w; bi = 4 * j + 3; }
            unsigned u = ordf(best);
            unsigned wm = __reduce_max_sync(0xffffffffu, u);
            unsigned bal = __ballot_sync(0xffffffffu, u == wm);
            int src = __ffs(bal) - 1;
            bi = __shfl_sync(0xffffffffu, bi, src);
            if (j == 0) g_lasttag[b] = bi;
        }
    }
}

// ---------------- K3: traceback --------------------------------------
// 16 blocks x 256 threads; each warp runs TWO independent batch chains
// interleaved to hide the redux/ballot/shfl latency. Branchless.
__global__ void k_traceback(const int* __restrict__ mask, float* __restrict__ out_tags) {
    extern __shared__ float sT[]; // transT[128][128]
    for (int idx = threadIdx.x; idx < NN * NN; idx += 256) sT[idx] = g_transT[idx];
    __syncthreads();

    const int w = threadIdx.x >> 5;
    const int l = threadIdx.x & 31;
    const int wg = blockIdx.x * 8 + w;
    const int b0 = 2 * wg;
    const int b1 = 2 * wg + 1;

    const float* A0 = g_alpha + (size_t)b0 * TT * NN;
    const float* A1 = g_alpha + (size_t)b1 * TT * NN;
    const int* mk0 = mask + (size_t)b0 * TT;
    const int* mk1 = mask + (size_t)b1 * TT;
    float* o0 = out_tags + (size_t)b0 * TT;
    float* o1 = out_tags + (size_t)b1 * TT;

    int tag0 = g_lasttag[b0];
    int tag1 = g_lasttag[b1];
    if (l == 0) {
        o0[TT - 1] = (float)tag0;
        o1[TT - 1] = (float)tag1;
    }

    float4 a0 = ((const float4*)(A0 + (size_t)(TT - 2) * NN))[l];
    float4 a1 = ((const float4*)(A1 + (size_t)(TT - 2) * NN))[l];
    int m0n = mk0[TT - 1];
    int m1n = mk1[TT - 1];

    for (int t = TT - 2; t >= 0; t--) {
        const int tp = (t > 0) ? (t - 1) : 0;
        // unconditional prefetch (clamped)
        float4 a0n = ((const float4*)(A0 + (size_t)tp * NN))[l];
        float4 a1n = ((const float4*)(A1 + (size_t)tp * NN))[l];
        int m0 = m0n, m1 = m1n;
        m0n = mk0[t];
        m1n = mk1[t];

        // chain 0
        {
            float4 Tv = ((const float4*)(sT + (size_t)tag0 * NN))[l];
            float v0 = a0.x + Tv.x, v1 = a0.y + Tv.y, v2 = a0.z + Tv.z, v3 = a0.w + Tv.w;
            float best = v0; int bi = 4 * l;
            if (v1 > best) { best = v1; bi = 4 * l + 1; }
            if (v2 > best) { best = v2; bi = 4 * l + 2; }
            if (v3 > best) { best = v3; bi = 4 * l + 3; }
            unsigned u = ordf(best);
            unsigned wm = __reduce_max_sync(0xffffffffu, u);
            unsigned bal = __ballot_sync(0xffffffffu, u == wm);
            int src = __ffs(bal) - 1;
            int nt = __shfl_sync(0xffffffffu, bi, src);
            tag0 = m0 ? nt : tag0;
        }
        // chain 1
        {
            float4 Tv = ((const float4*)(sT + (size_t)tag1 * NN))[l];
            float v0 = a1.x + Tv.x, v1 = a1.y + Tv.y, v2 = a1.z + Tv.z, v3 = a1.w + Tv.w;
            float best = v0; int bi = 4 * l;
            if (v1 > best) { best = v1; bi = 4 * l + 1; }
            if (v2 > best) { best = v2; bi = 4 * l + 2; }
            if (v3 > best) { best = v3; bi = 4 * l + 3; }
            unsigned u = ordf(best);
            unsigned wm = __reduce_max_sync(0xffffffffu, u);
            unsigned bal = __ballot_sync(0xffffffffu, u == wm);
            int src = __ffs(bal) - 1;
            int nt = __shfl_sync(0xffffffffu, bi, src);
            tag1 = m1 ? nt : tag1;
        }

        if (l == 0) {
            o0[t] = (float)tag0;
            o1[t] = (float)tag1;
        }
        a0 = a0n;
        a1 = a1n;
    }
}

// ---------------- launch ---------------------------------------------
extern "C" void kernel_launch(void* const* d_in, const int* in_sizes, int n_in,
                              void* d_out, int out_size) {
    const float* emis  = (const float*)d_in[0];
    const int*   tags  = (const int*)d_in[1];
    const int*   mask  = (const int*)d_in[2];
    const float* trans = (const float*)d_in[3];
    float* out = (float*)d_out;

    float* out_ll    = out;
    float* out_trans = out + BB;
    float* out_tags  = out + BB + NN * NN;

    cudaFuncSetAttribute(k_traceback, cudaFuncAttributeMaxDynamicSharedMemorySize,
                         NN * NN * (int)sizeof(float));

    k_prep<<<(NN * NN + 255) / 256, 256>>>(trans, out_trans);
    k_score<<<BB, 256>>>(emis, tags, mask, trans);
    k_recur<<<2 * BB, 128>>>(emis, mask, trans, out_ll);
    k_traceback<<<BB / 16, 256, NN * NN * (int)sizeof(float)>>>(mask, out_tags);
}

// round 6
// speedup vs baseline: 1.6065x; 1.6065x over previous
#include <cuda_runtime.h>
#include <cuda_bf16.h>
#include <cstdint>

// Problem constants
#define BB 256
#define TT 512
#define NN 128

// ---------------- device scratch ----------------
__device__ float g_E[NN * NN];        // exp(trans)
__device__ float g_transT[NN * NN];   // transT[j][i] = trans[i][j]
__device__ float g_score[BB];
__device__ float g_alpha[(size_t)BB * TT * NN]; // viterbi alphas, 64 MB
__device__ int   g_lasttag[BB];

__device__ __forceinline__ unsigned ordf(float f) {
    unsigned u = __float_as_uint(f);
    return u ^ (((int)u >> 31) | 0x80000000u);
}

__device__ __forceinline__ void ffma2(unsigned long long& d,
                                      unsigned long long a,
                                      unsigned long long b) {
    asm("fma.rn.f32x2 %0, %1, %2, %0;" : "+l"(d) : "l"(a), "l"(b));
}

__device__ __forceinline__ unsigned long long add2(unsigned long long a,
                                                   unsigned long long b) {
    unsigned long long d;
    asm("add.rn.f32x2 %0, %1, %2;" : "=l"(d) : "l"(a), "l"(b));
    return d;
}

__device__ __forceinline__ float lo32(unsigned long long v) {
    return __uint_as_float((unsigned)v);
}
__device__ __forceinline__ float hi32(unsigned long long v) {
    return __uint_as_float((unsigned)(v >> 32));
}

// ---------------- K0: prep -----------------------------------------
__global__ void k_prep(const float* __restrict__ trans, float* __restrict__ out_trans) {
    int idx = blockIdx.x * 256 + threadIdx.x;
    if (idx < NN * NN) {
        float v = trans[idx];
        g_E[idx] = __expf(v);
        int i = idx >> 7, j = idx & 127;
        g_transT[j * NN + i] = v;
        out_trans[idx] = v;
    }
}

// ---------------- K1: sequence score --------------------------------
// tag_ids: JAX silently emits int32 despite int64 declaration.
__global__ __launch_bounds__(256) void k_score(const float* __restrict__ emis,
                                               const int* __restrict__ tags,
                                               const int* __restrict__ mask,
                                               const float* __restrict__ trans) {
    __shared__ float sred[8];
    const int b = blockIdx.x;
    const int tid = threadIdx.x;
    float acc = 0.f;
    const float* eb = emis + (size_t)b * TT * NN;
    const int* tb = tags + (size_t)b * TT;
    const int* mb = mask + (size_t)b * TT;
    for (int t = tid; t < TT; t += 256) {
        int tg = tb[t];
        float mf = (float)mb[t];
        float u = eb[(size_t)t * NN + tg] * mf;
        float bi = 0.f;
        if (t > 0) {
            int tp = tb[t - 1];
            bi = trans[tp * NN + tg] * mf;
        }
        acc += u + bi;
    }
    #pragma unroll
    for (int o = 16; o; o >>= 1) acc += __shfl_xor_sync(0xffffffffu, acc, o);
    if ((tid & 31) == 0) sred[tid >> 5] = acc;
    __syncthreads();
    if (tid == 0) {
        float s = 0.f;
        #pragma unroll
        for (int i = 0; i < 8; i++) s += sred[i];
        g_score[b] = s;
    }
}

// ---------------- K2: fused recurrences, 2 batches per block ---------
// grid = 256. blockIdx&1 == 0 -> forward (log-norm), == 1 -> viterbi.
// Each block handles batches b0=2*(blockIdx>>1), b1=b0+1.
// Thread j owns output state j; matrix column cached in registers (shared
// across both batches). One __syncthreads() per time step.
__global__ __launch_bounds__(128, 2) void k_recur(const float* __restrict__ emis,
                                                  const int* __restrict__ mask,
                                                  const float* __restrict__ trans,
                                                  float* __restrict__ out_ll) {
    const int type = blockIdx.x & 1;
    const int b0 = (blockIdx.x >> 1) * 2;
    const int b1 = b0 + 1;
    const int j = threadIdx.x;

    __shared__ __align__(16) float buf[2][2][NN];   // [sel][batch][state]
    __shared__ float csm[2][2];
    __shared__ int smask[2][TT];

    const float* e0 = emis + (size_t)b0 * TT * NN;
    const float* e1 = emis + (size_t)b1 * TT * NN;

    for (int i = j; i < TT; i += NN) {
        smask[0][i] = mask[(size_t)b0 * TT + i];
        smask[1][i] = mask[(size_t)b1 * TT + i];
    }

    if (type == 0) {
        // forward: alpha'_j = log(sum_i p_i * E_ij) + c + emit
        unsigned long long E2[64];
        {
            const float* Ej = g_E + j;
            #pragma unroll
            for (int k = 0; k < 64; k++) {
                unsigned lo = __float_as_uint(Ej[(size_t)(2 * k) * NN]);
                unsigned hi = __float_as_uint(Ej[(size_t)(2 * k + 1) * NN]);
                E2[k] = (unsigned long long)lo | ((unsigned long long)hi << 32);
            }
        }

        float a0 = e0[j],  a1 = e1[j];
        float c0 = e0[0],  c1 = e1[0];
        float en0 = e0[NN + j], en1 = e1[NN + j];
        int sel = 0;
        __syncthreads();             // smask ready

        for (int t = 1; t < TT; t++) {
            buf[sel][0][j] = __expf(a0 - c0);
            buf[sel][1][j] = __expf(a1 - c1);
            if (j == 0) { csm[sel][0] = a0; csm[sel][1] = a1; }
            __syncthreads();
            float c0n = csm[sel][0], c1n = csm[sel][1];

            unsigned long long acc0[4] = {0ull, 0ull, 0ull, 0ull};
            unsigned long long acc1[4] = {0ull, 0ull, 0ull, 0ull};
            const ulonglong2* p0 = (const ulonglong2*)buf[sel][0];
            const ulonglong2* p1 = (const ulonglong2*)buf[sel][1];
            #pragma unroll
            for (int k = 0; k < 32; k++) {
                ulonglong2 v0 = p0[k];
                ulonglong2 v1 = p1[k];
                ffma2(acc0[(2 * k) & 3], v0.x, E2[2 * k]);
                ffma2(acc0[(2 * k + 1) & 3], v0.y, E2[2 * k + 1]);
                ffma2(acc1[(2 * k) & 3], v1.x, E2[2 * k]);
                ffma2(acc1[(2 * k + 1) & 3], v1.y, E2[2 * k + 1]);
            }
            float s0 = 0.f, s1 = 0.f;
            #pragma unroll
            for (int q = 0; q < 4; q++) {
                s0 += lo32(acc0[q]) + hi32(acc0[q]);
                s1 += lo32(acc1[q]) + hi32(acc1[q]);
            }

            float ec0 = en0, ec1 = en1;
            if (t + 1 < TT) {
                en0 = e0[(size_t)(t + 1) * NN + j];
                en1 = e1[(size_t)(t + 1) * NN + j];
            }

            float n0 = __logf(s0) + c0 + ec0;
            float n1 = __logf(s1) + c1 + ec1;
            a0 = smask[0][t] ? n0 : a0;
            a1 = smask[1][t] ? n1 : a1;
            c0 = c0n; c1 = c1n;
            sel ^= 1;
        }

        // final logsumexp, one warp per batch
        buf[0][0][j] = __expf(a0 - c0);
        buf[0][1][j] = __expf(a1 - c1);
        __syncthreads();
        const int wid = j >> 5;
        if (wid < 2) {
            const int l = j & 31;
            float4 v = ((const float4*)buf[0][wid])[l];
            float ts = (v.x + v.y) + (v.z + v.w);
            #pragma unroll
            for (int o = 16; o; o >>= 1) ts += __shfl_xor_sync(0xffffffffu, ts, o);
            if (l == 0) {
                int b = wid ? b1 : b0;
                float c = wid ? c1 : c0;
                out_ll[b] = g_score[b] - (__logf(ts) + c);
            }
        }
    } else {
        // viterbi: alpha'_j = max_i(a_i + T_ij) + emit
        // packed add2 (fma pipe) + scalar fmaxf (alu pipe)
        unsigned long long T2[64];
        {
            const float* Tj = trans + j;
            #pragma unroll
            for (int k = 0; k < 64; k++) {
                unsigned lo = __float_as_uint(Tj[(size_t)(2 * k) * NN]);
                unsigned hi = __float_as_uint(Tj[(size_t)(2 * k + 1) * NN]);
                T2[k] = (unsigned long long)lo | ((unsigned long long)hi << 32);
            }
        }

        float* ar0 = g_alpha + (size_t)b0 * TT * NN;
        float* ar1 = g_alpha + (size_t)b1 * TT * NN;
        float a0 = e0[j], a1 = e1[j];
        buf[0][0][j] = a0;
        buf[0][1][j] = a1;
        ar0[j] = a0;
        ar1[j] = a1;
        float en0 = e0[NN + j], en1 = e1[NN + j];
        int sel = 0;
        const float NEGINF = -3.402823466e38f;
        __syncthreads();             // buf[0] + smask ready

        for (int t = 1; t < TT; t++) {
            float m0[4] = {NEGINF, NEGINF, NEGINF, NEGINF};
            float m1[4] = {NEGINF, NEGINF, NEGINF, NEGINF};
            const ulonglong2* p0 = (const ulonglong2*)buf[sel][0];
            const ulonglong2* p1 = (const ulonglong2*)buf[sel][1];
            #pragma unroll
            for (int k = 0; k < 32; k++) {
                ulonglong2 v0 = p0[k];
                ulonglong2 v1 = p1[k];
                unsigned long long w00 = add2(v0.x, T2[2 * k]);
                unsigned long long w01 = add2(v0.y, T2[2 * k + 1]);
                unsigned long long w10 = add2(v1.x, T2[2 * k]);
                unsigned long long w11 = add2(v1.y, T2[2 * k + 1]);
                m0[0] = fmaxf(m0[0], lo32(w00));
                m0[1] = fmaxf(m0[1], hi32(w00));
                m0[2] = fmaxf(m0[2], lo32(w01));
                m0[3] = fmaxf(m0[3], hi32(w01));
                m1[0] = fmaxf(m1[0], lo32(w10));
                m1[1] = fmaxf(m1[1], hi32(w10));
                m1[2] = fmaxf(m1[2], lo32(w11));
                m1[3] = fmaxf(m1[3], hi32(w11));
            }
            float bm0 = fmaxf(fmaxf(m0[0], m0[1]), fmaxf(m0[2], m0[3]));
            float bm1 = fmaxf(fmaxf(m1[0], m1[1]), fmaxf(m1[2], m1[3]));

            float ec0 = en0, ec1 = en1;
            if (t + 1 < TT) {
                en0 = e0[(size_t)(t + 1) * NN + j];
                en1 = e1[(size_t)(t + 1) * NN + j];
            }

            float n0 = bm0 + ec0;
            float n1 = bm1 + ec1;
            a0 = smask[0][t] ? n0 : a0;
            a1 = smask[1][t] ? n1 : a1;
            buf[sel ^ 1][0][j] = a0;
            buf[sel ^ 1][1][j] = a1;
            ar0[(size_t)t * NN + j] = a0;
            ar1[(size_t)t * NN + j] = a1;
            sel ^= 1;
            __syncthreads();
        }

        // last_tag per batch: one warp each
        const int wid = j >> 5;
        if (wid < 2) {
            const int l = j & 31;
            float4 v = ((const float4*)buf[sel][wid])[l];
            float best = v.x; int bi = 4 * l;
            if (v.y > best) { best = v.y; bi = 4 * l + 1; }
            if (v.z > best) { best = v.z; bi = 4 * l + 2; }
            if (v.w > best) { best = v.w; bi = 4 * l + 3; }
            unsigned u = ordf(best);
            unsigned wm = __reduce_max_sync(0xffffffffu, u);
            unsigned bal = __ballot_sync(0xffffffffu, u == wm);
            int src = __ffs(bal) - 1;
            bi = __shfl_sync(0xffffffffu, bi, src);
            if (l == 0) g_lasttag[wid ? b1 : b0] = bi;
        }
    }
}

// ---------------- K3: traceback --------------------------------------
// 64 blocks x 128 threads; one batch chain per warp (each warp gets its
// own SMSP). transT cached in 64KB dynamic smem.
__global__ void k_traceback(const int* __restrict__ mask, float* __restrict__ out_tags) {
    extern __shared__ float sT[]; // transT[128][128]
    for (int idx = threadIdx.x; idx < NN * NN / 4; idx += 128)
        ((float4*)sT)[idx] = ((const float4*)g_transT)[idx];
    __syncthreads();

    const int w = threadIdx.x >> 5;
    const int l = threadIdx.x & 31;
    const int b = blockIdx.x * 4 + w;

    const float* arows = g_alpha + (size_t)b * TT * NN;
    const int* mb = mask + (size_t)b * TT;
    float* ot = out_tags + (size_t)b * TT;

    int tag = g_lasttag[b];
    if (l == 0) ot[TT - 1] = (float)tag;

    float4 A_next = ((const float4*)(arows + (size_t)(TT - 2) * NN))[l];
    int m_next = mb[TT - 1];

    for (int t = TT - 2; t >= 0; t--) {
        const int tp = (t > 0) ? (t - 1) : 0;
        float4 A = A_next; int m_cur = m_next;
        A_next = ((const float4*)(arows + (size_t)tp * NN))[l];
        m_next = mb[t];

        float4 Tv = ((const float4*)(sT + (size_t)tag * NN))[l];
        float v0 = A.x + Tv.x, v1 = A.y + Tv.y, v2 = A.z + Tv.z, v3 = A.w + Tv.w;
        float best = v0; int bi = 4 * l;
        if (v1 > best) { best = v1; bi = 4 * l + 1; }
        if (v2 > best) { best = v2; bi = 4 * l + 2; }
        if (v3 > best) { best = v3; bi = 4 * l + 3; }
        unsigned u = ordf(best);
        unsigned wm = __reduce_max_sync(0xffffffffu, u);
        unsigned bal = __ballot_sync(0xffffffffu, u == wm);
        int src = __ffs(bal) - 1;
        int nt = __shfl_sync(0xffffffffu, bi, src);
        tag = m_cur ? nt : tag;

        if (l == 0) ot[t] = (float)tag;
    }
}

// ---------------- launch ---------------------------------------------
extern "C" void kernel_launch(void* const* d_in, const int* in_sizes, int n_in,
                              void* d_out, int out_size) {
    const float* emis  = (const float*)d_in[0];
    const int*   tags  = (const int*)d_in[1];
    const int*   mask  = (const int*)d_in[2];
    const float* trans = (const float*)d_in[3];
    float* out = (float*)d_out;

    float* out_ll    = out;
    float* out_trans = out + BB;
    float* out_tags  = out + BB + NN * NN;

    cudaFuncSetAttribute(k_traceback, cudaFuncAttributeMaxDynamicSharedMemorySize,
                         NN * NN * (int)sizeof(float));

    k_prep<<<(NN * NN + 255) / 256, 256>>>(trans, out_trans);
    k_score<<<BB, 256>>>(emis, tags, mask, trans);
    k_recur<<<BB, 128>>>(emis, mask, trans, out_ll);
    k_traceback<<<BB / 4, 128, NN * NN * (int)sizeof(float)>>>(mask, out_tags);
}

// round 7
// speedup vs baseline: 1.8968x; 1.1807x over previous
#include <cuda_runtime.h>
#include <cuda_bf16.h>
#include <cstdint>

// Problem constants
#define BB 256
#define TT 512
#define NN 128

// ---------------- device scratch ----------------
__device__ float g_E[NN * NN];                 // exp(trans)
__device__ float g_score[BB];
__device__ unsigned char g_bp[(size_t)BB * TT * NN]; // backpointers, 16.7 MB
__device__ int   g_lasttag[BB];

__device__ __forceinline__ unsigned ordf(float f) {
    unsigned u = __float_as_uint(f);
    return u ^ (((int)u >> 31) | 0x80000000u);
}

__device__ __forceinline__ void ffma2(unsigned long long& d,
                                      unsigned long long a,
                                      unsigned long long b) {
    asm("fma.rn.f32x2 %0, %1, %2, %0;" : "+l"(d) : "l"(a), "l"(b));
}

__device__ __forceinline__ unsigned long long add2(unsigned long long a,
                                                   unsigned long long b) {
    unsigned long long d;
    asm("add.rn.f32x2 %0, %1, %2;" : "=l"(d) : "l"(a), "l"(b));
    return d;
}

__device__ __forceinline__ float lo32(unsigned long long v) {
    return __uint_as_float((unsigned)v);
}
__device__ __forceinline__ float hi32(unsigned long long v) {
    return __uint_as_float((unsigned)(v >> 32));
}

// ---------------- K0: prep -----------------------------------------
__global__ void k_prep(const float* __restrict__ trans, float* __restrict__ out_trans) {
    int idx = blockIdx.x * 256 + threadIdx.x;
    if (idx < NN * NN) {
        float v = trans[idx];
        g_E[idx] = __expf(v);
        out_trans[idx] = v;
    }
}

// ---------------- K1: sequence score --------------------------------
// tag_ids: JAX silently emits int32 despite int64 declaration.
__global__ __launch_bounds__(256) void k_score(const float* __restrict__ emis,
                                               const int* __restrict__ tags,
                                               const int* __restrict__ mask,
                                               const float* __restrict__ trans) {
    __shared__ float sred[8];
    const int b = blockIdx.x;
    const int tid = threadIdx.x;
    float acc = 0.f;
    const float* eb = emis + (size_t)b * TT * NN;
    const int* tb = tags + (size_t)b * TT;
    const int* mb = mask + (size_t)b * TT;
    for (int t = tid; t < TT; t += 256) {
        int tg = tb[t];
        float mf = (float)mb[t];
        float u = eb[(size_t)t * NN + tg] * mf;
        float bi = 0.f;
        if (t > 0) {
            int tp = tb[t - 1];
            bi = trans[tp * NN + tg] * mf;
        }
        acc += u + bi;
    }
    #pragma unroll
    for (int o = 16; o; o >>= 1) acc += __shfl_xor_sync(0xffffffffu, acc, o);
    if ((tid & 31) == 0) sred[tid >> 5] = acc;
    __syncthreads();
    if (tid == 0) {
        float s = 0.f;
        #pragma unroll
        for (int i = 0; i < 8; i++) s += sred[i];
        g_score[b] = s;
    }
}

// ---------------- K2: fused recurrences, 2 batches per block ---------
// grid = 256. blockIdx&1 == 0 -> forward (log-norm), == 1 -> viterbi.
// Each block handles batches b0=2*(blockIdx>>1), b1=b0+1.
// Thread j owns output state j; matrix column cached in registers.
// Viterbi additionally computes exact first-index argmax (backpointers)
// via contiguous group maxima + rescan of the winning group.
__global__ __launch_bounds__(128, 2) void k_recur(const float* __restrict__ emis,
                                                  const int* __restrict__ mask,
                                                  const float* __restrict__ trans,
                                                  float* __restrict__ out_ll) {
    extern __shared__ float transS[];   // 64KB, viterbi blocks only (row-major trans)

    const int type = blockIdx.x & 1;
    const int b0 = (blockIdx.x >> 1) * 2;
    const int b1 = b0 + 1;
    const int j = threadIdx.x;

    __shared__ __align__(16) float buf[2][2][NN];   // [sel][batch][state]
    __shared__ float csm[2][2];
    __shared__ int smask[2][TT];

    const float* e0 = emis + (size_t)b0 * TT * NN;
    const float* e1 = emis + (size_t)b1 * TT * NN;

    for (int i = j; i < TT; i += NN) {
        smask[0][i] = mask[(size_t)b0 * TT + i];
        smask[1][i] = mask[(size_t)b1 * TT + i];
    }

    if (type == 0) {
        // forward: alpha'_j = log(sum_i p_i * E_ij) + c + emit
        unsigned long long E2[64];
        {
            const float* Ej = g_E + j;
            #pragma unroll
            for (int k = 0; k < 64; k++) {
                unsigned lo = __float_as_uint(Ej[(size_t)(2 * k) * NN]);
                unsigned hi = __float_as_uint(Ej[(size_t)(2 * k + 1) * NN]);
                E2[k] = (unsigned long long)lo | ((unsigned long long)hi << 32);
            }
        }

        float a0 = e0[j],  a1 = e1[j];
        float c0 = e0[0],  c1 = e1[0];
        float en0 = e0[NN + j], en1 = e1[NN + j];
        int sel = 0;
        __syncthreads();             // smask ready

        for (int t = 1; t < TT; t++) {
            buf[sel][0][j] = __expf(a0 - c0);
            buf[sel][1][j] = __expf(a1 - c1);
            if (j == 0) { csm[sel][0] = a0; csm[sel][1] = a1; }
            __syncthreads();
            float c0n = csm[sel][0], c1n = csm[sel][1];

            unsigned long long acc0[4] = {0ull, 0ull, 0ull, 0ull};
            unsigned long long acc1[4] = {0ull, 0ull, 0ull, 0ull};
            const ulonglong2* p0 = (const ulonglong2*)buf[sel][0];
            const ulonglong2* p1 = (const ulonglong2*)buf[sel][1];
            #pragma unroll
            for (int k = 0; k < 32; k++) {
                ulonglong2 v0 = p0[k];
                ulonglong2 v1 = p1[k];
                ffma2(acc0[(2 * k) & 3], v0.x, E2[2 * k]);
                ffma2(acc0[(2 * k + 1) & 3], v0.y, E2[2 * k + 1]);
                ffma2(acc1[(2 * k) & 3], v1.x, E2[2 * k]);
                ffma2(acc1[(2 * k + 1) & 3], v1.y, E2[2 * k + 1]);
            }
            float s0 = 0.f, s1 = 0.f;
            #pragma unroll
            for (int q = 0; q < 4; q++) {
                s0 += lo32(acc0[q]) + hi32(acc0[q]);
                s1 += lo32(acc1[q]) + hi32(acc1[q]);
            }

            float ec0 = en0, ec1 = en1;
            if (t + 1 < TT) {
                en0 = e0[(size_t)(t + 1) * NN + j];
                en1 = e1[(size_t)(t + 1) * NN + j];
            }

            float n0 = __logf(s0) + c0 + ec0;
            float n1 = __logf(s1) + c1 + ec1;
            a0 = smask[0][t] ? n0 : a0;
            a1 = smask[1][t] ? n1 : a1;
            c0 = c0n; c1 = c1n;
            sel ^= 1;
        }

        // final logsumexp, one warp per batch
        buf[0][0][j] = __expf(a0 - c0);
        buf[0][1][j] = __expf(a1 - c1);
        __syncthreads();
        const int wid = j >> 5;
        if (wid < 2) {
            const int l = j & 31;
            float4 v = ((const float4*)buf[0][wid])[l];
            float ts = (v.x + v.y) + (v.z + v.w);
            #pragma unroll
            for (int o = 16; o; o >>= 1) ts += __shfl_xor_sync(0xffffffffu, ts, o);
            if (l == 0) {
                int b = wid ? b1 : b0;
                float c = wid ? c1 : c0;
                out_ll[b] = g_score[b] - (__logf(ts) + c);
            }
        }
    } else {
        // viterbi: alpha'_j = max_i(a_i + T_ij) + emit, with backpointers.
        // Contiguous group maxima m[q] over i in [16q, 16q+16).
        unsigned long long T2[64];
        {
            const float* Tj = trans + j;
            #pragma unroll
            for (int k = 0; k < 64; k++) {
                unsigned lo = __float_as_uint(Tj[(size_t)(2 * k) * NN]);
                unsigned hi = __float_as_uint(Tj[(size_t)(2 * k + 1) * NN]);
                T2[k] = (unsigned long long)lo | ((unsigned long long)hi << 32);
            }
        }
        // row-major trans copy in smem for the rescan (per-lane distinct banks)
        for (int idx = j; idx < NN * NN / 4; idx += NN)
            ((float4*)transS)[idx] = ((const float4*)trans)[idx];

        unsigned char* bp0 = g_bp + (size_t)b0 * TT * NN;
        unsigned char* bp1 = g_bp + (size_t)b1 * TT * NN;
        float a0 = e0[j], a1 = e1[j];
        buf[0][0][j] = a0;
        buf[0][1][j] = a1;
        float en0 = e0[NN + j], en1 = e1[NN + j];
        int sel = 0;
        const float NEGINF = -3.402823466e38f;
        __syncthreads();             // buf[0] + smask + transS ready

        for (int t = 1; t < TT; t++) {
            float m0[8], m1[8];
            #pragma unroll
            for (int q = 0; q < 8; q++) { m0[q] = NEGINF; m1[q] = NEGINF; }
            const ulonglong2* p0 = (const ulonglong2*)buf[sel][0];
            const ulonglong2* p1 = (const ulonglong2*)buf[sel][1];
            #pragma unroll
            for (int k = 0; k < 32; k++) {           // cands 4k..4k+3, group k>>2
                ulonglong2 v0 = p0[k];
                ulonglong2 v1 = p1[k];
                unsigned long long w00 = add2(v0.x, T2[2 * k]);
                unsigned long long w01 = add2(v0.y, T2[2 * k + 1]);
                unsigned long long w10 = add2(v1.x, T2[2 * k]);
                unsigned long long w11 = add2(v1.y, T2[2 * k + 1]);
                const int q = k >> 2;
                m0[q] = fmaxf(m0[q], lo32(w00));
                m0[q] = fmaxf(m0[q], hi32(w00));
                m0[q] = fmaxf(m0[q], lo32(w01));
                m0[q] = fmaxf(m0[q], hi32(w01));
                m1[q] = fmaxf(m1[q], lo32(w10));
                m1[q] = fmaxf(m1[q], hi32(w10));
                m1[q] = fmaxf(m1[q], lo32(w11));
                m1[q] = fmaxf(m1[q], hi32(w11));
            }
            float bm0 = fmaxf(fmaxf(fmaxf(m0[0], m0[1]), fmaxf(m0[2], m0[3])),
                              fmaxf(fmaxf(m0[4], m0[5]), fmaxf(m0[6], m0[7])));
            float bm1 = fmaxf(fmaxf(fmaxf(m1[0], m1[1]), fmaxf(m1[2], m1[3])),
                              fmaxf(fmaxf(m1[4], m1[5]), fmaxf(m1[6], m1[7])));

            // first group attaining the max
            int g0 = 7, g1 = 7;
            #pragma unroll
            for (int q = 6; q >= 0; q--) {
                g0 = (m0[q] == bm0) ? q : g0;
                g1 = (m1[q] == bm1) ? q : g1;
            }

            // rescan winning group: first index with candidate == bm
            int u0 = 15, u1 = 15;
            {
                const float* al0 = buf[sel][0] + 16 * g0;
                const float* al1 = buf[sel][1] + 16 * g1;
                float av0[16], av1[16];
                #pragma unroll
                for (int r = 0; r < 4; r++) {
                    float4 x0 = ((const float4*)al0)[r];
                    float4 x1 = ((const float4*)al1)[r];
                    av0[4 * r] = x0.x; av0[4 * r + 1] = x0.y;
                    av0[4 * r + 2] = x0.z; av0[4 * r + 3] = x0.w;
                    av1[4 * r] = x1.x; av1[4 * r + 1] = x1.y;
                    av1[4 * r + 2] = x1.z; av1[4 * r + 3] = x1.w;
                }
                const float* ts0 = transS + (size_t)(16 * g0) * NN + j;
                const float* ts1 = transS + (size_t)(16 * g1) * NN + j;
                #pragma unroll
                for (int r = 15; r >= 0; r--) {
                    float c0v = av0[r] + ts0[(size_t)r * NN];
                    float c1v = av1[r] + ts1[(size_t)r * NN];
                    u0 = (c0v == bm0) ? r : u0;
                    u1 = (c1v == bm1) ? r : u1;
                }
            }

            float ec0 = en0, ec1 = en1;
            if (t + 1 < TT) {
                en0 = e0[(size_t)(t + 1) * NN + j];
                en1 = e1[(size_t)(t + 1) * NN + j];
            }

            int msk0 = smask[0][t], msk1 = smask[1][t];
            float n0 = bm0 + ec0;
            float n1 = bm1 + ec1;
            a0 = msk0 ? n0 : a0;
            a1 = msk1 ? n1 : a1;
            int v0i = msk0 ? (16 * g0 + u0) : j;
            int v1i = msk1 ? (16 * g1 + u1) : j;
            bp0[(size_t)t * NN + j] = (unsigned char)v0i;
            bp1[(size_t)t * NN + j] = (unsigned char)v1i;
            buf[sel ^ 1][0][j] = a0;
            buf[sel ^ 1][1][j] = a1;
            sel ^= 1;
            __syncthreads();
        }

        // last_tag per batch: one warp each (first-index argmax)
        const int wid = j >> 5;
        if (wid < 2) {
            const int l = j & 31;
            float4 v = ((const float4*)buf[sel][wid])[l];
            float best = v.x; int bi = 4 * l;
            if (v.y > best) { best = v.y; bi = 4 * l + 1; }
            if (v.z > best) { best = v.z; bi = 4 * l + 2; }
            if (v.w > best) { best = v.w; bi = 4 * l + 3; }
            unsigned u = ordf(best);
            unsigned wm = __reduce_max_sync(0xffffffffu, u);
            unsigned bal = __ballot_sync(0xffffffffu, u == wm);
            int src = __ffs(bal) - 1;
            bi = __shfl_sync(0xffffffffu, bi, src);
            if (l == 0) g_lasttag[wid ? b1 : b0] = bi;
        }
    }
}

// ---------------- K3: traceback (smem byte chase) --------------------
// One block per batch: load the 64KB bp slab into smem, then one thread
// chases tag = sbp[(t+1)*128 + tag]. No warp collectives, ~35cyc/step.
__global__ __launch_bounds__(128) void k_traceback(float* __restrict__ out_tags) {
    extern __shared__ unsigned char sbp[];  // 64KB
    const int b = blockIdx.x;

    const float4* src = (const float4*)(g_bp + (size_t)b * TT * NN);
    #pragma unroll
    for (int i = 0; i < 32; i++)
        ((float4*)sbp)[threadIdx.x + i * 128] = src[threadIdx.x + i * 128];
    __syncthreads();

    if (threadIdx.x == 0) {
        float* ot = out_tags + (size_t)b * TT;
        int tag = g_lasttag[b];
        ot[TT - 1] = (float)tag;
        for (int t = TT - 2; t >= 0; t--) {
            tag = sbp[(t + 1) * NN + tag];
            ot[t] = (float)tag;
        }
    }
}

// ---------------- launch ---------------------------------------------
extern "C" void kernel_launch(void* const* d_in, const int* in_sizes, int n_in,
                              void* d_out, int out_size) {
    const float* emis  = (const float*)d_in[0];
    const int*   tags  = (const int*)d_in[1];
    const int*   mask  = (const int*)d_in[2];
    const float* trans = (const float*)d_in[3];
    float* out = (float*)d_out;

    float* out_ll    = out;
    float* out_trans = out + BB;
    float* out_tags  = out + BB + NN * NN;

    const int SM64 = NN * NN * (int)sizeof(float);   // 64KB
    cudaFuncSetAttribute(k_recur, cudaFuncAttributeMaxDynamicSharedMemorySize, SM64);
    cudaFuncSetAttribute(k_traceback, cudaFuncAttributeMaxDynamicSharedMemorySize, SM64);

    k_prep<<<(NN * NN + 255) / 256, 256>>>(trans, out_trans);
    k_score<<<BB, 256>>>(emis, tags, mask, trans);
    k_recur<<<BB, 128, SM64>>>(emis, mask, trans, out_ll);
    k_traceback<<<BB, 128, SM64>>>(out_tags);
}